// round 9
// baseline (speedup 1.0000x reference)
#include <cuda_runtime.h>
#include <math.h>

#define S_LEN 128
#define B_SZ  64
#define H_SZ  512
#define O_SZ  256
#define NMAX  8
#define NBLK  64

typedef unsigned long long u64;

// ---------------- device scratch (static; allocation is forbidden) ----------------
__device__ __align__(16) float g_preT[S_LEN * H_SZ * B_SZ];   // [t][j][b]
__device__ __align__(16) float g_accsT[S_LEN * H_SZ * B_SZ];  // [t][j][b]
__device__ __align__(16) float g_hbuf[3 * H_SZ * B_SZ];       // triple-buffer [buf][k][b]
__device__ unsigned g_flag[NBLK * 32];                        // per-block flag, 128B stride

__device__ __forceinline__ void ffma2(u64 &d, u64 a, u64 b) {
    asm("fma.rn.f32x2 %0, %1, %2, %0;" : "+l"(d) : "l"(a), "l"(b));
}
__device__ __forceinline__ float lo32(u64 v) { return __uint_as_float((unsigned)(v & 0xffffffffu)); }
__device__ __forceinline__ float hi32(u64 v) { return __uint_as_float((unsigned)(v >> 32)); }
__device__ __forceinline__ u64 pack2(float x, float y) {
    return ((u64)__float_as_uint(y) << 32) | (u64)__float_as_uint(x);
}
__device__ __forceinline__ unsigned ld_acq(unsigned* p) {
    unsigned v;
    asm volatile("ld.acquire.gpu.u32 %0, [%1];" : "=r"(v) : "l"(p) : "memory");
    return v;
}
__device__ __forceinline__ void st_rel(unsigned* p, unsigned v) {
    asm volatile("st.release.gpu.u32 [%0], %1;" :: "l"(p), "r"(v) : "memory");
}

// ---------------- kernel 1: pre-projection GEMM ----------------
__global__ void __launch_bounds__(256) pre_gemm(const float* __restrict__ x,
                                                const float* __restrict__ W_ih,
                                                const float* __restrict__ b_ih,
                                                const float* __restrict__ b_hh) {
    __shared__ float Xs[64 * 65];
    __shared__ float Ws[64 * 65];
    const int t = blockIdx.y, jt = blockIdx.x;
    const int tid = threadIdx.x;
    const int ty = tid >> 4, tx = tid & 15;
    float acc[4][4] = {};
    for (int kc = 0; kc < 4; ++kc) {
        __syncthreads();
        for (int i = tid; i < 4096; i += 256) {
            int r = i >> 6, kk = i & 63;
            Xs[r * 65 + kk] = x[(t * 64 + r) * 256 + kc * 64 + kk];
            Ws[r * 65 + kk] = W_ih[(jt * 64 + r) * 257 + 1 + kc * 64 + kk];
        }
        __syncthreads();
        #pragma unroll 8
        for (int kk = 0; kk < 64; ++kk) {
            float wv[4], xv[4];
            #pragma unroll
            for (int a = 0; a < 4; ++a) wv[a] = Ws[(ty * 4 + a) * 65 + kk];
            #pragma unroll
            for (int c = 0; c < 4; ++c) xv[c] = Xs[(tx * 4 + c) * 65 + kk];
            #pragma unroll
            for (int a = 0; a < 4; ++a)
                #pragma unroll
                for (int c = 0; c < 4; ++c)
                    acc[a][c] = fmaf(wv[a], xv[c], acc[a][c]);
        }
    }
    #pragma unroll
    for (int a = 0; a < 4; ++a) {
        int j = jt * 64 + ty * 4 + a;
        float bias = b_ih[j] + b_hh[j];
        #pragma unroll
        for (int c = 0; c < 4; ++c) {
            int b = tx * 4 + c;
            g_preT[(t * 512 + j) * 64 + b] = acc[a][c] + bias;
        }
    }
}

// ---------------- init: s -> buf0 [k][b]; reset flags (self-heal every launch) ----------------
__global__ void init_h(const float* __restrict__ s) {
    if (threadIdx.x == 0) g_flag[blockIdx.x * 32] = 0u;
    int b = blockIdx.x;
    int j = threadIdx.x;
    g_hbuf[j * 64 + b] = s[b * 512 + j];
}

// ---------------- kernel 2: persistent ACT recurrence ----------------
// Dataflow-flag pipeline with the halt dot-product FUSED into the GEMM
// (the streamed h is last step's h_new, so sum_k W_halt[k]*h[k] computed
// alongside the recurrent GEMM IS the lagged halt logit — no side channel).
// Halt state (cum/halted/pond) is replicated in per-thread registers across
// all warps; all blocks compute identical decisions from identical global
// data in identical order => uniform control flow, no divergent waits.
__global__ void __launch_bounds__(256, 1) rnn_act(const float* __restrict__ W_hh,
                                                  const float* __restrict__ W_ih,
                                                  const float* __restrict__ W_halt,
                                                  const float* __restrict__ b_halt,
                                                  float* __restrict__ pond_out) {
    __shared__ __align__(16) u64 sh_W2[4096];      // [k=512][j=8] dup-pairs (32 KB)
    __shared__ __align__(16) u64 sh_part[4 * 288]; // [grp=4][slot=9][lane=32] (9 KB)
    __shared__ __align__(16) u64 sh_whalt2[512];   // W_halt dup-pairs [k]      (4 KB)
    __shared__ float sh_wih0[8];
    __shared__ float sh_bhalt;

    const int blk  = blockIdx.x;
    const int tid  = threadIdx.x;
    const int warp = tid >> 5, lane = tid & 31;
    const int j = warp, b0 = lane * 2;             // thread <-> (j, b-pair) mapping
    const int gj = blk * 8 + j;

    // one-time: W_hh slice + W_halt -> SMEM as duplicated f32x2 pairs
    for (int i = tid; i < 4096; i += 256) {
        int jj = i >> 9, k = i & 511;
        unsigned wb = __float_as_uint(W_hh[(blk * 8 + jj) * 512 + k]);
        sh_W2[k * 8 + jj] = ((u64)wb << 32) | (u64)wb;
    }
    for (int i = tid; i < 512; i += 256) {
        unsigned wb = __float_as_uint(W_halt[i]);
        sh_whalt2[i] = ((u64)wb << 32) | (u64)wb;
    }
    if (tid < 8) sh_wih0[tid] = W_ih[(blk * 8 + tid) * 257];
    if (tid == 0) sh_bhalt = b_halt[0];
    __syncthreads();

    unsigned m = 0;               // global step counter (monotonic)
    int m3 = 0, nx3 = 1;          // m % 3, (m+1) % 3
    int t = 0, n = 0;             // timestep, local ponder index (uniform)
    float accx = 0.f, accy = 0.f; // acc_s for (j, b0/b0+1)
    float hpx = 0.f, hpy = 0.f;   // previous-step h for (j, b0/b0+1)
    float cumx = 0.f, cumy = 0.f; // replicated halt state for (b0, b0+1)
    int   hlx = 0, hly = 0;
    float pondx = 0.f, pondy = 0.f;

    const int fidx = (warp << 3) + (lane < 8 ? lane : 0);
    unsigned* myflag = &g_flag[fidx << 5];
    const float bhalt = b_halt[0];
    (void)bhalt;

    while (t < S_LEN) {
        // prefetch this step's pre-projection before the wait
        const float2 pre2 = __ldg((const float2*)(g_preT + ((t * 512 + gj) << 6) + b0));
        // ---- wait: one vectorized readiness check (8 producers per warp) ----
        for (;;) {
            unsigned v = (lane < 8) ? ld_acq(myflag) : 0xffffffffu;
            if (__all_sync(0xffffffffu, v >= m)) break;
            __nanosleep(32);
        }
        // ---- GEMM + fused halt dot, software-pipelined loads (8-deep) ----
        u64 q0=0,q1=0,q2=0,q3=0,q4=0,q5=0,q6=0,q7=0,q8=0;
        {
            const u64* rp = (const u64*)g_hbuf + m3 * 16384 + (warp << 11) + lane;
            u64 cur[8];
            #pragma unroll
            for (int kk = 0; kk < 8; ++kk) cur[kk] = __ldcg(rp + (kk << 5));
            #pragma unroll
            for (int c8 = 0; c8 < 8; ++c8) {
                u64 nxt[8];
                if (c8 < 7) {
                    #pragma unroll
                    for (int kk = 0; kk < 8; ++kk)
                        nxt[kk] = __ldcg(rp + ((((c8 + 1) << 3) + kk) << 5));
                }
                #pragma unroll
                for (int kk = 0; kk < 8; ++kk) {
                    const int kr = (c8 << 3) + kk;
                    u64 h2 = cur[kk];
                    const ulonglong2* wr = (const ulonglong2*)(sh_W2 + (((warp << 6) + kr) << 3));
                    ulonglong2 w01 = wr[0], w23 = wr[1], w45 = wr[2], w67 = wr[3];
                    ffma2(q0, h2, w01.x); ffma2(q1, h2, w01.y);
                    ffma2(q2, h2, w23.x); ffma2(q3, h2, w23.y);
                    ffma2(q4, h2, w45.x); ffma2(q5, h2, w45.y);
                    ffma2(q6, h2, w67.x); ffma2(q7, h2, w67.y);
                    ffma2(q8, h2, sh_whalt2[(warp << 6) + kr]);
                }
                if (c8 < 7) {
                    #pragma unroll
                    for (int kk = 0; kk < 8; ++kk) cur[kk] = nxt[kk];
                }
            }
        }
        // ---- stage 9 partial slots (warps 0-3), then fold (warps 4-7) ----
        if (warp < 4) {
            u64* pp = sh_part + warp * 288 + lane;
            pp[0*32]=q0; pp[1*32]=q1; pp[2*32]=q2; pp[3*32]=q3;
            pp[4*32]=q4; pp[5*32]=q5; pp[6*32]=q6; pp[7*32]=q7; pp[8*32]=q8;
        }
        __syncthreads();
        if (warp >= 4) {
            u64* pp = sh_part + (warp - 4) * 288 + lane;
            u64 v;
            v = pp[0*32]; pp[0*32] = pack2(lo32(v)+lo32(q0), hi32(v)+hi32(q0));
            v = pp[1*32]; pp[1*32] = pack2(lo32(v)+lo32(q1), hi32(v)+hi32(q1));
            v = pp[2*32]; pp[2*32] = pack2(lo32(v)+lo32(q2), hi32(v)+hi32(q2));
            v = pp[3*32]; pp[3*32] = pack2(lo32(v)+lo32(q3), hi32(v)+hi32(q3));
            v = pp[4*32]; pp[4*32] = pack2(lo32(v)+lo32(q4), hi32(v)+hi32(q4));
            v = pp[5*32]; pp[5*32] = pack2(lo32(v)+lo32(q5), hi32(v)+hi32(q5));
            v = pp[6*32]; pp[6*32] = pack2(lo32(v)+lo32(q6), hi32(v)+hi32(q6));
            v = pp[7*32]; pp[7*32] = pack2(lo32(v)+lo32(q7), hi32(v)+hi32(q7));
            v = pp[8*32]; pp[8*32] = pack2(lo32(v)+lo32(q8), hi32(v)+hi32(q8));
        }
        __syncthreads();
        // ---- finalize lagged halting for ponder q=n-1 (replicated, registers) ----
        if (n >= 1) {
            float lx = 0.f, ly = 0.f;
            #pragma unroll
            for (int g = 0; g < 4; ++g) {
                u64 v = sh_part[g * 288 + 8 * 32 + lane];
                lx += lo32(v); ly += hi32(v);
            }
            float px = 1.f / (1.f + expf(-(lx + sh_bhalt)));
            float py = 1.f / (1.f + expf(-(ly + sh_bhalt)));
            if (hlx) px = 0.f;
            if (hly) py = 0.f;
            int ihx = (!hlx) && (((cumx + px) >= 0.99f) || (n - 1 == NMAX - 1));
            int ihy = (!hly) && (((cumy + py) >= 0.99f) || (n - 1 == NMAX - 1));
            float wx = ihx ? (1.f - cumx) : px;
            float wy = ihy ? (1.f - cumy) : py;
            if (ihx) pondx = (1.f - cumx) + (float)n;
            if (ihy) pondy = (1.f - cumy) + (float)n;
            cumx += px; cumy += py;
            hlx |= ihx; hly |= ihy;
            accx += wx * hpx; accy += wy * hpy;
        }
        const int allh = __all_sync(0xffffffffu, hlx && hly);   // one warp spans all 64 b
        // ---- j-reduce + tanh -> h_new, or write carry ----
        u64* bw = (u64*)g_hbuf + nx3 * 16384 + (gj << 5) + lane;
        if (!allh) {
            float sx = 0.f, sy = 0.f;
            #pragma unroll
            for (int g = 0; g < 4; ++g) {
                u64 v = sh_part[g * 288 + j * 32 + lane];
                sx += lo32(v); sy += hi32(v);
            }
            float ax = sx + pre2.x, ay = sy + pre2.y;
            if (n == 0) { float f = sh_wih0[j]; ax += f; ay += f; }
            hpx = tanhf(ax); hpy = tanhf(ay);
            *bw = pack2(hpx, hpy);
        } else {
            *bw = pack2(accx, accy);   // carry = acc_s -> next timestep's h input
        }
        __syncthreads();
        // ---- release (critical path ends here) ----
        if (tid == 0) st_rel(&g_flag[blk << 5], m + 1);
        // ---- off-path housekeeping ----
        if (!allh) {
            ++n;
        } else {
            *(float2*)(g_accsT + ((t * 512 + gj) << 6) + b0) = make_float2(accx, accy);
            if (blk == 0 && warp == 0) {
                pond_out[t * 64 + b0]     = pondx;
                pond_out[t * 64 + b0 + 1] = pondy;
            }
            cumx = cumy = 0.f; hlx = hly = 0; pondx = pondy = 0.f;
            accx = accy = 0.f;
            ++t; n = 0;
        }
        ++m;
        m3 = nx3; nx3 = (nx3 + 1 == 3) ? 0 : nx3 + 1;
    }
}

// ---------------- kernel 3: output GEMM ----------------
__global__ void __launch_bounds__(256) out_gemm(const float* __restrict__ W_out,
                                                const float* __restrict__ b_out,
                                                float* __restrict__ out) {
    __shared__ float As[64 * 65];
    __shared__ float Ws[64 * 65];
    const int t = blockIdx.y, ot = blockIdx.x;
    const int tid = threadIdx.x;
    const int ty = tid >> 4, tx = tid & 15;
    float acc[4][4] = {};
    for (int kc = 0; kc < 8; ++kc) {
        __syncthreads();
        for (int i = tid; i < 4096; i += 256) {
            int r = i >> 6, c = i & 63;
            As[r * 65 + c] = g_accsT[(t * 512 + kc * 64 + r) * 64 + c];
            Ws[r * 65 + c] = W_out[(ot * 64 + r) * 512 + kc * 64 + c];
        }
        __syncthreads();
        #pragma unroll 8
        for (int kk = 0; kk < 64; ++kk) {
            float wv[4], xv[4];
            #pragma unroll
            for (int a = 0; a < 4; ++a) wv[a] = Ws[(ty * 4 + a) * 65 + kk];
            #pragma unroll
            for (int c = 0; c < 4; ++c) xv[c] = As[kk * 65 + tx * 4 + c];
            #pragma unroll
            for (int a = 0; a < 4; ++a)
                #pragma unroll
                for (int c = 0; c < 4; ++c)
                    acc[a][c] = fmaf(wv[a], xv[c], acc[a][c]);
        }
    }
    #pragma unroll
    for (int a = 0; a < 4; ++a) {
        int o = ot * 64 + ty * 4 + a;
        float bias = b_out[o];
        #pragma unroll
        for (int c = 0; c < 4; ++c) {
            int b = tx * 4 + c;
            out[(t * 64 + b) * 256 + o] = acc[a][c] + bias;
        }
    }
}

extern "C" void kernel_launch(void* const* d_in, const int* in_sizes, int n_in,
                              void* d_out, int out_size) {
    const float* x      = (const float*)d_in[0];
    const float* s      = (const float*)d_in[1];
    const float* W_ih   = (const float*)d_in[2];
    const float* b_ih   = (const float*)d_in[3];
    const float* W_hh   = (const float*)d_in[4];
    const float* b_hh   = (const float*)d_in[5];
    const float* W_out  = (const float*)d_in[6];
    const float* b_out  = (const float*)d_in[7];
    const float* W_halt = (const float*)d_in[8];
    const float* b_halt = (const float*)d_in[9];
    float* out  = (float*)d_out;                       // outputs [S,B,O]
    float* pond = out + S_LEN * B_SZ * O_SZ;           // ponder  [S,B]

    dim3 preg(8, S_LEN);
    pre_gemm<<<preg, 256>>>(x, W_ih, b_ih, b_hh);
    init_h<<<B_SZ, H_SZ>>>(s);
    rnn_act<<<NBLK, 256>>>(W_hh, W_ih, W_halt, b_halt, pond);
    dim3 outg(4, S_LEN);
    out_gemm<<<outg, 256>>>(W_out, b_out, out);
}